// round 15
// baseline (speedup 1.0000x reference)
#include <cuda_runtime.h>
#include <cuda_bf16.h>
#include <stdint.h>

#define BB   8
#define CCH  128
#define NN   4096
#define DD   16
#define NCO  160

#define XS_STRIDE 136
#define WS_STRIDE 136

#define KS_STRIDE 24     // bf16 per K smem row
#define VS_STRIDE 136    // bf16 per V smem row

// scratch
__device__ __nv_bfloat16 g_Q[(size_t)BB*NN*DD];
__device__ __nv_bfloat16 g_K[(size_t)BB*NN*DD];
__device__ __nv_bfloat16 g_V[(size_t)BB*NN*CCH];

// ---------------- helpers ----------------
__device__ __forceinline__ uint32_t smem_u32(const void* p){
  return (uint32_t)__cvta_generic_to_shared(p);
}
__device__ __forceinline__ void mma_bf16(float &c0,float &c1,float &c2,float &c3,
    uint32_t a0,uint32_t a1,uint32_t a2,uint32_t a3,uint32_t b0,uint32_t b1){
  asm volatile("mma.sync.aligned.m16n8k16.row.col.f32.bf16.bf16.f32 "
    "{%0,%1,%2,%3}, {%4,%5,%6,%7}, {%8,%9}, {%0,%1,%2,%3};\n"
    : "+f"(c0),"+f"(c1),"+f"(c2),"+f"(c3)
    : "r"(a0),"r"(a1),"r"(a2),"r"(a3),"r"(b0),"r"(b1));
}
__device__ __forceinline__ void ldsm_x4_t(uint32_t &r0,uint32_t &r1,uint32_t &r2,uint32_t &r3,uint32_t addr){
  asm volatile("ldmatrix.sync.aligned.m8n8.x4.trans.shared.b16 {%0,%1,%2,%3}, [%4];\n"
   : "=r"(r0),"=r"(r1),"=r"(r2),"=r"(r3) : "r"(addr));
}
__device__ __forceinline__ void cp_async16(uint32_t dst, const void* src){
  asm volatile("cp.async.cg.shared.global [%0], [%1], 16;\n" :: "r"(dst), "l"(src));
}
__device__ __forceinline__ float fast_exp2(float xx){
  float y; asm("ex2.approx.ftz.f32 %0, %1;" : "=f"(y) : "f"(xx)); return y;
}
__device__ __forceinline__ uint32_t pack_bf162(float lo, float hi){
  uint32_t r; asm("cvt.rn.bf16x2.f32 %0, %1, %2;" : "=r"(r) : "f"(hi), "f"(lo)); return r;
}

// ---------------- Kernel 1: fused QKV projection (vectorized; 2 CTAs/SM) ----------------
__global__ void __launch_bounds__(256, 2) qkv_proj_kernel(
    const float* __restrict__ x,
    const float* __restrict__ qw, const float* __restrict__ qb,
    const float* __restrict__ kw, const float* __restrict__ kb,
    const float* __restrict__ vw, const float* __restrict__ vb)
{
  extern __shared__ char smem[];
  __nv_bfloat16* Xs = (__nv_bfloat16*)smem;
  __nv_bfloat16* Ws = (__nv_bfloat16*)(smem + 128*XS_STRIDE*2);
  float* bias_s     = (float*)(smem + 128*XS_STRIDE*2 + NCO*WS_STRIDE*2);

  const int tid  = threadIdx.x;
  const int b    = blockIdx.x >> 5;
  const int n0   = (blockIdx.x & 31) << 7;
  const int lane = tid & 31;
  const int warp = tid >> 5;
  const int qd   = lane & 3, rr = lane >> 2;

  for (int idx = tid; idx < NCO*CCH/2; idx += 256){
    int e = idx*2;
    int row = e >> 7, c = e & 127;
    float v0, v1;
    if (row < 16)     { v0 = qw[row*CCH + c]; v1 = qw[row*CCH + c + 1]; }
    else if (row < 32){ v0 = kw[(row-16)*CCH + c]; v1 = kw[(row-16)*CCH + c + 1]; }
    else              { v0 = vw[(row-32)*CCH + c]; v1 = vw[(row-32)*CCH + c + 1]; }
    *(uint32_t*)(Ws + row*WS_STRIDE + c) = pack_bf162(v0, v1);
  }
  if (tid < NCO)
    bias_s[tid] = (tid < 16) ? qb[tid] : (tid < 32) ? kb[tid-16] : vb[tid-32];

  {
    int c = tid >> 1, half = tid & 1;
    const float4* src = (const float4*)(x + ((size_t)b*CCH + c)*NN + n0 + half*64);
    __nv_bfloat16* dst = Xs + c*XS_STRIDE + half*64;
    #pragma unroll
    for (int jj = 0; jj < 16; jj++){
      float4 v = src[jj];
      uint2 pk;
      pk.x = pack_bf162(v.x, v.y);
      pk.y = pack_bf162(v.z, v.w);
      *(uint2*)(dst + jj*4) = pk;
    }
  }
  __syncthreads();

  const int m0 = warp << 4;
  uint32_t a[8][4];
  {
    int krow = (lane & 7) + ((lane & 16) ? 8 : 0);
    int mcol = m0 + ((lane & 8) ? 8 : 0);
    #pragma unroll
    for (int kc = 0; kc < 8; kc++){
      uint32_t addr = smem_u32(Xs + (kc*16 + krow)*XS_STRIDE + mcol);
      ldsm_x4_t(a[kc][0], a[kc][1], a[kc][2], a[kc][3], addr);
    }
  }

  float acc[20][4];
  #pragma unroll
  for (int t = 0; t < 20; t++){ acc[t][0]=0.f; acc[t][1]=0.f; acc[t][2]=0.f; acc[t][3]=0.f; }

  #pragma unroll
  for (int ct = 0; ct < 20; ct++){
    const __nv_bfloat16* wrow = Ws + (ct*8 + rr)*WS_STRIDE;
    #pragma unroll
    for (int kc = 0; kc < 8; kc++){
      uint32_t b0 = *(const uint32_t*)(wrow + kc*16 + 2*qd);
      uint32_t b1 = *(const uint32_t*)(wrow + kc*16 + 2*qd + 8);
      mma_bf16(acc[ct][0],acc[ct][1],acc[ct][2],acc[ct][3],
               a[kc][0],a[kc][1],a[kc][2],a[kc][3], b0, b1);
    }
  }

  const float LOG2E = 1.4426950408889634f;
  const int n1 = n0 + m0 + rr;
  #pragma unroll
  for (int ct = 0; ct < 20; ct++){
    int co = ct*8 + 2*qd;
    float b0v = bias_s[co], b1v = bias_s[co+1];
    float v00 = acc[ct][0] + b0v, v01 = acc[ct][1] + b1v;
    float v10 = acc[ct][2] + b0v, v11 = acc[ct][3] + b1v;
    if (co < 16){
      v00*=LOG2E; v01*=LOG2E; v10*=LOG2E; v11*=LOG2E;
      *(uint32_t*)(g_Q + ((size_t)b*NN + n1    )*DD + co) = pack_bf162(v00, v01);
      *(uint32_t*)(g_Q + ((size_t)b*NN + n1 + 8)*DD + co) = pack_bf162(v10, v11);
    } else if (co < 32){
      *(uint32_t*)(g_K + ((size_t)b*NN + n1    )*DD + (co-16)) = pack_bf162(v00, v01);
      *(uint32_t*)(g_K + ((size_t)b*NN + n1 + 8)*DD + (co-16)) = pack_bf162(v10, v11);
    } else {
      *(uint32_t*)(g_V + ((size_t)b*NN + n1    )*CCH + (co-32)) = pack_bf162(v00, v01);
      *(uint32_t*)(g_V + ((size_t)b*NN + n1 + 8)*CCH + (co-32)) = pack_bf162(v10, v11);
    }
  }
}

// ---------------- Kernel 2: flash attention, 64q/CTA, 2 CTAs/SM ----------------
// 256 thr, 8 warps = 4 qt (16q) x 2 kh (64-key half). Round-8 warp body unchanged.
// smem: K0 @0 (6144) | K1 @6144 | V0 @12288 (34816) | V1 @47104 | total 81920
// epilogue overlay: osm [64][129] f32 (33024) | l_sm[128] @33024 | inv[64] @33536
#define SM_K0 0
#define SM_K1 6144
#define SM_V0 12288
#define SM_V1 47104
#define SM_TOTAL 81920
#define OSM_STRIDE 129
#define SM_LSM 33024
#define SM_INV 33536

__global__ void __launch_bounds__(256, 2) attn11_kernel(
    const float* __restrict__ x, const float* __restrict__ gamma_p,
    float* __restrict__ out)
{
  extern __shared__ char smem[];
  const uint32_t sb = smem_u32(smem);

  const int tid  = threadIdx.x;
  const int b    = blockIdx.x >> 6;
  const int n0   = (blockIdx.x & 63) << 6;
  const int lane = tid & 31;
  const int warp = tid >> 5;
  const int qt   = warp & 3;     // 16-query tile (64 q per CTA)
  const int kh   = warp >> 2;    // key half
  const int qd   = lane & 3, rr = lane >> 2;

  const size_t kv_base = (size_t)b * NN;

  // Q A-fragment
  uint32_t qa[4];
  {
    const __nv_bfloat16* base = g_Q + (kv_base + n0 + qt*16)*DD;
    qa[0] = *(const uint32_t*)(base + (rr  )*DD + 2*qd);
    qa[1] = *(const uint32_t*)(base + (rr+8)*DD + 2*qd);
    qa[2] = *(const uint32_t*)(base + (rr  )*DD + 2*qd + 8);
    qa[3] = *(const uint32_t*)(base + (rr+8)*DD + 2*qd + 8);
  }

  float O[16][4];
  #pragma unroll
  for (int j = 0; j < 16; j++){ O[j][0]=0.f; O[j][1]=0.f; O[j][2]=0.f; O[j][3]=0.f; }
  float l_acc0 = 0.f, l_acc1 = 0.f;

  const uint32_t kbufs[2] = { sb + SM_K0, sb + SM_K1 };
  const uint32_t vbufs[2] = { sb + SM_V0, sb + SM_V1 };

  // preload chunk 0 (128 keys)
  {
    int row = tid >> 1, seg = tid & 1;
    cp_async16(kbufs[0] + row*(KS_STRIDE*2) + seg*16,
               g_K + (kv_base + row)*DD + seg*8);
    #pragma unroll
    for (int i = 0; i < 8; i++){
      int id = tid + 256*i;
      int vr = id >> 4, sg = id & 15;
      cp_async16(vbufs[0] + vr*(VS_STRIDE*2) + sg*16,
                 g_V + (kv_base + vr)*CCH + sg*8);
    }
  }
  asm volatile("cp.async.commit_group;\n" ::: "memory");

  const int vrow = lane & 15;
  const int vcol = (lane >> 4) * 8;

  for (int it = 0; it < 32; it++){
    const int buf = it & 1;

    asm volatile("cp.async.wait_group 0;\n" ::: "memory");
    __syncthreads();

    // prefetch it+1
    if (it + 1 < 32){
      const int k0 = (it + 1) << 7;
      const int nb = buf ^ 1;
      int row = tid >> 1, seg = tid & 1;
      cp_async16(kbufs[nb] + row*(KS_STRIDE*2) + seg*16,
                 g_K + (kv_base + k0 + row)*DD + seg*8);
      #pragma unroll
      for (int i = 0; i < 8; i++){
        int id = tid + 256*i;
        int vr = id >> 4, sg = id & 15;
        cp_async16(vbufs[nb] + vr*(VS_STRIDE*2) + sg*16,
                   g_V + (kv_base + k0 + vr)*CCH + sg*8);
      }
      asm volatile("cp.async.commit_group;\n" ::: "memory");
    }

    // ---- QK: 16q x 64k ----
    float s[8][4];
    {
      const __nv_bfloat16* ksb = (const __nv_bfloat16*)(smem + (buf ? SM_K1 : SM_K0));
      #pragma unroll
      for (int tt = 0; tt < 8; tt++){
        const __nv_bfloat16* krow = ksb + (kh*64 + tt*8 + rr)*KS_STRIDE;
        uint32_t kb0 = *(const uint32_t*)(krow + 2*qd);
        uint32_t kb1 = *(const uint32_t*)(krow + 2*qd + 8);
        s[tt][0]=0.f; s[tt][1]=0.f; s[tt][2]=0.f; s[tt][3]=0.f;
        mma_bf16(s[tt][0],s[tt][1],s[tt][2],s[tt][3],
                 qa[0],qa[1],qa[2],qa[3], kb0,kb1);
      }
    }

    // ---- exp + pack ----
    uint32_t pa[4][4];
    #pragma unroll
    for (int kc = 0; kc < 4; kc++){
      float e00 = fast_exp2(s[2*kc  ][0]);
      float e01 = fast_exp2(s[2*kc  ][1]);
      float e02 = fast_exp2(s[2*kc  ][2]);
      float e03 = fast_exp2(s[2*kc  ][3]);
      float e10 = fast_exp2(s[2*kc+1][0]);
      float e11 = fast_exp2(s[2*kc+1][1]);
      float e12 = fast_exp2(s[2*kc+1][2]);
      float e13 = fast_exp2(s[2*kc+1][3]);
      l_acc0 += (e00 + e01) + (e10 + e11);
      l_acc1 += (e02 + e03) + (e12 + e13);
      pa[kc][0] = pack_bf162(e00, e01);
      pa[kc][1] = pack_bf162(e02, e03);
      pa[kc][2] = pack_bf162(e10, e11);
      pa[kc][3] = pack_bf162(e12, e13);
    }

    // ---- PV over own 64 keys: 16q x 128c ----
    {
      const uint32_t vtile = vbufs[buf] + (kh*64 + vrow)*(VS_STRIDE*2) + vcol*2;
      #pragma unroll
      for (int kc = 0; kc < 4; kc++){
        #pragma unroll
        for (int nt = 0; nt < 8; nt++){
          uint32_t v0,v1,v2,v3;
          ldsm_x4_t(v0,v1,v2,v3, vtile + kc*16*(VS_STRIDE*2) + nt*32);
          mma_bf16(O[2*nt  ][0],O[2*nt  ][1],O[2*nt  ][2],O[2*nt  ][3],
                   pa[kc][0],pa[kc][1],pa[kc][2],pa[kc][3], v0,v1);
          mma_bf16(O[2*nt+1][0],O[2*nt+1][1],O[2*nt+1][2],O[2*nt+1][3],
                   pa[kc][0],pa[kc][1],pa[kc][2],pa[kc][3], v2,v3);
        }
      }
    }
  }

  // ---- epilogue (round-10 verified 64q layout) ----
  __syncthreads();
  float* osm  = (float*)smem;                  // [64][OSM_STRIDE]
  float* l_sm = (float*)(smem + SM_LSM);       // [128] = 2 kh x 64 q
  float* inv  = (float*)(smem + SM_INV);       // [64]

  l_acc0 += __shfl_xor_sync(0xffffffffu, l_acc0, 1);
  l_acc0 += __shfl_xor_sync(0xffffffffu, l_acc0, 2);
  l_acc1 += __shfl_xor_sync(0xffffffffu, l_acc1, 1);
  l_acc1 += __shfl_xor_sync(0xffffffffu, l_acc1, 2);
  if (qd == 0){
    int qb0 = kh*64 + qt*16;
    l_sm[qb0 + rr    ] = l_acc0;
    l_sm[qb0 + rr + 8] = l_acc1;
  }
  if (kh == 1){
    int q0 = qt*16 + rr, q1 = q0 + 8;
    #pragma unroll
    for (int j = 0; j < 16; j++){
      int c = j*8 + 2*qd;
      osm[q0*OSM_STRIDE + c    ] = O[j][0];
      osm[q0*OSM_STRIDE + c + 1] = O[j][1];
      osm[q1*OSM_STRIDE + c    ] = O[j][2];
      osm[q1*OSM_STRIDE + c + 1] = O[j][3];
    }
  }
  __syncthreads();
  if (kh == 0){
    int q0 = qt*16 + rr, q1 = q0 + 8;
    #pragma unroll
    for (int j = 0; j < 16; j++){
      int c = j*8 + 2*qd;
      osm[q0*OSM_STRIDE + c    ] += O[j][0];
      osm[q0*OSM_STRIDE + c + 1] += O[j][1];
      osm[q1*OSM_STRIDE + c    ] += O[j][2];
      osm[q1*OSM_STRIDE + c + 1] += O[j][3];
    }
  }
  if (tid < 64){
    inv[tid] = (*gamma_p) / (l_sm[tid] + l_sm[64 + tid]);
  }
  __syncthreads();

  // coalesced writeout: warp w owns channels {w, w+8, ...}, lanes span 64 n
  #pragma unroll
  for (int cc = 0; cc < 16; cc++){
    int c = warp + 8*cc;
    size_t rowbase = ((size_t)b*CCH + c)*NN + n0;
    #pragma unroll
    for (int nn = 0; nn < 2; nn++){
      int n = lane + 32*nn;
      out[rowbase + n] = osm[n*OSM_STRIDE + c]*inv[n] + x[rowbase + n];
    }
  }
}

extern "C" void kernel_launch(void* const* d_in, const int* in_sizes, int n_in,
                              void* d_out, int out_size) {
  const float* x  = (const float*)d_in[0];
  const float* qw = (const float*)d_in[1];
  const float* qb = (const float*)d_in[2];
  const float* kw = (const float*)d_in[3];
  const float* kb = (const float*)d_in[4];
  const float* vw = (const float*)d_in[5];
  const float* vb = (const float*)d_in[6];
  const float* gm = (const float*)d_in[7];
  float* out = (float*)d_out;

  const int proj_smem = 128*XS_STRIDE*2 + NCO*WS_STRIDE*2 + NCO*4;
  cudaFuncSetAttribute(qkv_proj_kernel, cudaFuncAttributeMaxDynamicSharedMemorySize, proj_smem);
  cudaFuncSetAttribute(attn11_kernel,   cudaFuncAttributeMaxDynamicSharedMemorySize, SM_TOTAL);

  qkv_proj_kernel<<<BB*32, 256, proj_smem>>>(x, qw, qb, kw, kb, vw, vb);
  attn11_kernel<<<BB*64, 256, SM_TOTAL>>>(x, gm, out);
}

// round 16
// speedup vs baseline: 1.1411x; 1.1411x over previous
#include <cuda_runtime.h>
#include <cuda_bf16.h>
#include <cuda_fp16.h>
#include <stdint.h>

#define BB   8
#define CCH  128
#define NN   4096
#define DD   16
#define NCO  160

#define XS_STRIDE 136
#define WS_STRIDE 136

#define KS_STRIDE 24     // bf16 per K smem row
#define VS_STRIDE 136    // fp16 per V smem row

// scratch
__device__ __nv_bfloat16 g_Q[(size_t)BB*NN*DD];
__device__ __nv_bfloat16 g_K[(size_t)BB*NN*DD];
__device__ __half        g_V[(size_t)BB*NN*CCH];

// ---------------- helpers ----------------
__device__ __forceinline__ uint32_t smem_u32(const void* p){
  return (uint32_t)__cvta_generic_to_shared(p);
}
__device__ __forceinline__ void mma_bf16(float &c0,float &c1,float &c2,float &c3,
    uint32_t a0,uint32_t a1,uint32_t a2,uint32_t a3,uint32_t b0,uint32_t b1){
  asm volatile("mma.sync.aligned.m16n8k16.row.col.f32.bf16.bf16.f32 "
    "{%0,%1,%2,%3}, {%4,%5,%6,%7}, {%8,%9}, {%0,%1,%2,%3};\n"
    : "+f"(c0),"+f"(c1),"+f"(c2),"+f"(c3)
    : "r"(a0),"r"(a1),"r"(a2),"r"(a3),"r"(b0),"r"(b1));
}
__device__ __forceinline__ void mma_f16f32(float &c0,float &c1,float &c2,float &c3,
    uint32_t a0,uint32_t a1,uint32_t a2,uint32_t a3,uint32_t b0,uint32_t b1){
  asm volatile("mma.sync.aligned.m16n8k16.row.col.f32.f16.f16.f32 "
    "{%0,%1,%2,%3}, {%4,%5,%6,%7}, {%8,%9}, {%0,%1,%2,%3};\n"
    : "+f"(c0),"+f"(c1),"+f"(c2),"+f"(c3)
    : "r"(a0),"r"(a1),"r"(a2),"r"(a3),"r"(b0),"r"(b1));
}
__device__ __forceinline__ void ldsm_x4_t(uint32_t &r0,uint32_t &r1,uint32_t &r2,uint32_t &r3,uint32_t addr){
  asm volatile("ldmatrix.sync.aligned.m8n8.x4.trans.shared.b16 {%0,%1,%2,%3}, [%4];\n"
   : "=r"(r0),"=r"(r1),"=r"(r2),"=r"(r3) : "r"(addr));
}
__device__ __forceinline__ void cp_async16(uint32_t dst, const void* src){
  asm volatile("cp.async.cg.shared.global [%0], [%1], 16;\n" :: "r"(dst), "l"(src));
}
__device__ __forceinline__ uint32_t pack_bf162(float lo, float hi){
  uint32_t r; asm("cvt.rn.bf16x2.f32 %0, %1, %2;" : "=r"(r) : "f"(hi), "f"(lo)); return r;
}
__device__ __forceinline__ uint32_t f2h2(float lo, float hi){
  __half2 h = __floats2half2_rn(lo, hi); return *(uint32_t*)&h;
}
__device__ __forceinline__ uint32_t exp2h2(uint32_t x){
  uint32_t y; asm("ex2.approx.f16x2 %0, %1;" : "=r"(y) : "r"(x)); return y;
}
__device__ __forceinline__ uint32_t hadd2u(uint32_t a, uint32_t b){
  uint32_t d; asm("add.rn.f16x2 %0, %1, %2;" : "=r"(d) : "r"(a), "r"(b)); return d;
}

// ---------------- Kernel 1: fused QKV projection (V -> fp16; 2 CTAs/SM) ----------------
__global__ void __launch_bounds__(256, 2) qkv_proj_kernel(
    const float* __restrict__ x,
    const float* __restrict__ qw, const float* __restrict__ qb,
    const float* __restrict__ kw, const float* __restrict__ kb,
    const float* __restrict__ vw, const float* __restrict__ vb)
{
  extern __shared__ char smem[];
  __nv_bfloat16* Xs = (__nv_bfloat16*)smem;
  __nv_bfloat16* Ws = (__nv_bfloat16*)(smem + 128*XS_STRIDE*2);
  float* bias_s     = (float*)(smem + 128*XS_STRIDE*2 + NCO*WS_STRIDE*2);

  const int tid  = threadIdx.x;
  const int b    = blockIdx.x >> 5;
  const int n0   = (blockIdx.x & 31) << 7;
  const int lane = tid & 31;
  const int warp = tid >> 5;
  const int qd   = lane & 3, rr = lane >> 2;

  for (int idx = tid; idx < NCO*CCH/2; idx += 256){
    int e = idx*2;
    int row = e >> 7, c = e & 127;
    float v0, v1;
    if (row < 16)     { v0 = qw[row*CCH + c]; v1 = qw[row*CCH + c + 1]; }
    else if (row < 32){ v0 = kw[(row-16)*CCH + c]; v1 = kw[(row-16)*CCH + c + 1]; }
    else              { v0 = vw[(row-32)*CCH + c]; v1 = vw[(row-32)*CCH + c + 1]; }
    *(uint32_t*)(Ws + row*WS_STRIDE + c) = pack_bf162(v0, v1);
  }
  if (tid < NCO)
    bias_s[tid] = (tid < 16) ? qb[tid] : (tid < 32) ? kb[tid-16] : vb[tid-32];

  {
    int c = tid >> 1, half = tid & 1;
    const float4* src = (const float4*)(x + ((size_t)b*CCH + c)*NN + n0 + half*64);
    __nv_bfloat16* dst = Xs + c*XS_STRIDE + half*64;
    #pragma unroll
    for (int jj = 0; jj < 16; jj++){
      float4 v = src[jj];
      uint2 pk;
      pk.x = pack_bf162(v.x, v.y);
      pk.y = pack_bf162(v.z, v.w);
      *(uint2*)(dst + jj*4) = pk;
    }
  }
  __syncthreads();

  const int m0 = warp << 4;
  uint32_t a[8][4];
  {
    int krow = (lane & 7) + ((lane & 16) ? 8 : 0);
    int mcol = m0 + ((lane & 8) ? 8 : 0);
    #pragma unroll
    for (int kc = 0; kc < 8; kc++){
      uint32_t addr = smem_u32(Xs + (kc*16 + krow)*XS_STRIDE + mcol);
      ldsm_x4_t(a[kc][0], a[kc][1], a[kc][2], a[kc][3], addr);
    }
  }

  float acc[20][4];
  #pragma unroll
  for (int t = 0; t < 20; t++){ acc[t][0]=0.f; acc[t][1]=0.f; acc[t][2]=0.f; acc[t][3]=0.f; }

  #pragma unroll
  for (int ct = 0; ct < 20; ct++){
    const __nv_bfloat16* wrow = Ws + (ct*8 + rr)*WS_STRIDE;
    #pragma unroll
    for (int kc = 0; kc < 8; kc++){
      uint32_t b0 = *(const uint32_t*)(wrow + kc*16 + 2*qd);
      uint32_t b1 = *(const uint32_t*)(wrow + kc*16 + 2*qd + 8);
      mma_bf16(acc[ct][0],acc[ct][1],acc[ct][2],acc[ct][3],
               a[kc][0],a[kc][1],a[kc][2],a[kc][3], b0, b1);
    }
  }

  const float LOG2E = 1.4426950408889634f;
  const int n1 = n0 + m0 + rr;
  #pragma unroll
  for (int ct = 0; ct < 20; ct++){
    int co = ct*8 + 2*qd;
    float b0v = bias_s[co], b1v = bias_s[co+1];
    float v00 = acc[ct][0] + b0v, v01 = acc[ct][1] + b1v;
    float v10 = acc[ct][2] + b0v, v11 = acc[ct][3] + b1v;
    if (co < 16){
      v00*=LOG2E; v01*=LOG2E; v10*=LOG2E; v11*=LOG2E;
      *(uint32_t*)(g_Q + ((size_t)b*NN + n1    )*DD + co) = pack_bf162(v00, v01);
      *(uint32_t*)(g_Q + ((size_t)b*NN + n1 + 8)*DD + co) = pack_bf162(v10, v11);
    } else if (co < 32){
      *(uint32_t*)(g_K + ((size_t)b*NN + n1    )*DD + (co-16)) = pack_bf162(v00, v01);
      *(uint32_t*)(g_K + ((size_t)b*NN + n1 + 8)*DD + (co-16)) = pack_bf162(v10, v11);
    } else {
      *(uint32_t*)(g_V + ((size_t)b*NN + n1    )*CCH + (co-32)) = f2h2(v00, v01);
      *(uint32_t*)(g_V + ((size_t)b*NN + n1 + 8)*CCH + (co-32)) = f2h2(v10, v11);
    }
  }
}

// ---------------- Kernel 2: flash attention, 256-key chunks, f16x2 exp ----------------
// 512 thr, 16 warps = 8 qt x 2 kh. Round-14 structure, exp via ex2.approx.f16x2.
// smem: K0 @0 (12288) | K1 @12288 | V0 @24576 (69632) | V1 @94208 | total 163840
// epilogue overlay: osm [128][129] f32 @0 (66048) | l_sm[256] @66048 | inv[128] @67072
#define NIT 16
#define SM_K0 0
#define SM_K1 12288
#define SM_V0 24576
#define SM_V1 94208
#define SM_TOTAL 163840
#define OSM_STRIDE 129
#define SM_LSM 66048
#define SM_INV 67072

__global__ void __launch_bounds__(512, 1) attn12_kernel(
    const float* __restrict__ x, const float* __restrict__ gamma_p,
    float* __restrict__ out)
{
  extern __shared__ char smem[];
  const uint32_t sb = smem_u32(smem);

  const int tid  = threadIdx.x;
  const int b    = blockIdx.x >> 5;
  const int n0   = (blockIdx.x & 31) << 7;
  const int lane = tid & 31;
  const int warp = tid >> 5;
  const int qt   = warp & 7;     // 16-query tile
  const int kh   = warp >> 3;    // key half (within each 128-key sub-chunk)
  const int qd   = lane & 3, rr = lane >> 2;

  const size_t kv_base = (size_t)b * NN;

  // Q A-fragment
  uint32_t qa[4];
  {
    const __nv_bfloat16* base = g_Q + (kv_base + n0 + qt*16)*DD;
    qa[0] = *(const uint32_t*)(base + (rr  )*DD + 2*qd);
    qa[1] = *(const uint32_t*)(base + (rr+8)*DD + 2*qd);
    qa[2] = *(const uint32_t*)(base + (rr  )*DD + 2*qd + 8);
    qa[3] = *(const uint32_t*)(base + (rr+8)*DD + 2*qd + 8);
  }

  float O[16][4];
  #pragma unroll
  for (int j = 0; j < 16; j++){ O[j][0]=0.f; O[j][1]=0.f; O[j][2]=0.f; O[j][3]=0.f; }
  float l_acc0 = 0.f, l_acc1 = 0.f;

  const uint32_t kbufs[2] = { sb + SM_K0, sb + SM_K1 };
  const uint32_t vbufs[2] = { sb + SM_V0, sb + SM_V1 };

  // preload chunk 0 (256 keys)
  {
    int row = tid >> 1, seg = tid & 1;     // 256 rows x 2 segs
    cp_async16(kbufs[0] + row*(KS_STRIDE*2) + seg*16,
               g_K + (kv_base + row)*DD + seg*8);
    #pragma unroll
    for (int i = 0; i < 8; i++){
      int id = tid + 512*i;                // 4096 x 16B
      int vr = id >> 4, sg = id & 15;
      cp_async16(vbufs[0] + vr*(VS_STRIDE*2) + sg*16,
                 g_V + (kv_base + vr)*CCH + sg*8);
    }
  }
  asm volatile("cp.async.commit_group;\n" ::: "memory");

  const int vrow = lane & 15;
  const int vcol = (lane >> 4) * 8;

  for (int it = 0; it < NIT; it++){
    const int buf = it & 1;

    asm volatile("cp.async.wait_group 0;\n" ::: "memory");
    __syncthreads();

    // prefetch chunk it+1
    if (it + 1 < NIT){
      const int k0 = (it + 1) << 8;
      const int nb = buf ^ 1;
      int row = tid >> 1, seg = tid & 1;
      cp_async16(kbufs[nb] + row*(KS_STRIDE*2) + seg*16,
                 g_K + (kv_base + k0 + row)*DD + seg*8);
      #pragma unroll
      for (int i = 0; i < 8; i++){
        int id = tid + 512*i;
        int vr = id >> 4, sg = id & 15;
        cp_async16(vbufs[nb] + vr*(VS_STRIDE*2) + sg*16,
                   g_V + (kv_base + k0 + vr)*CCH + sg*8);
      }
      asm volatile("cp.async.commit_group;\n" ::: "memory");
    }

    // two 128-key sub-chunks
    const __nv_bfloat16* ksb = (const __nv_bfloat16*)(smem + (buf ? SM_K1 : SM_K0));
    #pragma unroll
    for (int sc = 0; sc < 2; sc++){
      const int kbase = sc*128 + kh*64;

      // ---- QK: 16q x 64k ----
      float s[8][4];
      #pragma unroll
      for (int tt = 0; tt < 8; tt++){
        const __nv_bfloat16* krow = ksb + (kbase + tt*8 + rr)*KS_STRIDE;
        uint32_t kb0 = *(const uint32_t*)(krow + 2*qd);
        uint32_t kb1 = *(const uint32_t*)(krow + 2*qd + 8);
        s[tt][0]=0.f; s[tt][1]=0.f; s[tt][2]=0.f; s[tt][3]=0.f;
        mma_bf16(s[tt][0],s[tt][1],s[tt][2],s[tt][3],
                 qa[0],qa[1],qa[2],qa[3], kb0,kb1);
      }

      // ---- exp via ex2.approx.f16x2: output IS the fp16 P fragment ----
      uint32_t pa[4][4];
      uint32_t l2a = 0u, l2b = 0u;   // f16x2 partial sums (sub-chunk bounded)
      #pragma unroll
      for (int kc = 0; kc < 4; kc++){
        pa[kc][0] = exp2h2(f2h2(s[2*kc  ][0], s[2*kc  ][1]));  // row rr
        pa[kc][1] = exp2h2(f2h2(s[2*kc  ][2], s[2*kc  ][3]));  // row rr+8
        pa[kc][2] = exp2h2(f2h2(s[2*kc+1][0], s[2*kc+1][1]));
        pa[kc][3] = exp2h2(f2h2(s[2*kc+1][2], s[2*kc+1][3]));
        l2a = hadd2u(l2a, hadd2u(pa[kc][0], pa[kc][2]));
        l2b = hadd2u(l2b, hadd2u(pa[kc][1], pa[kc][3]));
      }
      {
        float2 fa = __half22float2(*(__half2*)&l2a);
        float2 fb = __half22float2(*(__half2*)&l2b);
        l_acc0 += fa.x + fa.y;
        l_acc1 += fb.x + fb.y;
      }

      // ---- PV (f16 x f16 -> f32) over own 64 keys: 16q x 128c ----
      const uint32_t vtile = vbufs[buf] + (kbase + vrow)*(VS_STRIDE*2) + vcol*2;
      #pragma unroll
      for (int kc = 0; kc < 4; kc++){
        #pragma unroll
        for (int nt = 0; nt < 8; nt++){
          uint32_t v0,v1,v2,v3;
          ldsm_x4_t(v0,v1,v2,v3, vtile + kc*16*(VS_STRIDE*2) + nt*32);
          mma_f16f32(O[2*nt  ][0],O[2*nt  ][1],O[2*nt  ][2],O[2*nt  ][3],
                     pa[kc][0],pa[kc][1],pa[kc][2],pa[kc][3], v0,v1);
          mma_f16f32(O[2*nt+1][0],O[2*nt+1][1],O[2*nt+1][2],O[2*nt+1][3],
                     pa[kc][0],pa[kc][1],pa[kc][2],pa[kc][3], v2,v3);
        }
      }
    }
  }

  // ---- epilogue (round-8/14 verified) ----
  __syncthreads();
  float* osm  = (float*)smem;                  // [128][OSM_STRIDE]
  float* l_sm = (float*)(smem + SM_LSM);       // [256]
  float* inv  = (float*)(smem + SM_INV);       // [128]

  l_acc0 += __shfl_xor_sync(0xffffffffu, l_acc0, 1);
  l_acc0 += __shfl_xor_sync(0xffffffffu, l_acc0, 2);
  l_acc1 += __shfl_xor_sync(0xffffffffu, l_acc1, 1);
  l_acc1 += __shfl_xor_sync(0xffffffffu, l_acc1, 2);
  if (qd == 0){
    int qb0 = kh*128 + qt*16;
    l_sm[qb0 + rr    ] = l_acc0;
    l_sm[qb0 + rr + 8] = l_acc1;
  }
  if (kh == 1){
    int q0 = qt*16 + rr, q1 = q0 + 8;
    #pragma unroll
    for (int j = 0; j < 16; j++){
      int c = j*8 + 2*qd;
      osm[q0*OSM_STRIDE + c    ] = O[j][0];
      osm[q0*OSM_STRIDE + c + 1] = O[j][1];
      osm[q1*OSM_STRIDE + c    ] = O[j][2];
      osm[q1*OSM_STRIDE + c + 1] = O[j][3];
    }
  }
  __syncthreads();
  if (kh == 0){
    int q0 = qt*16 + rr, q1 = q0 + 8;
    #pragma unroll
    for (int j = 0; j < 16; j++){
      int c = j*8 + 2*qd;
      osm[q0*OSM_STRIDE + c    ] += O[j][0];
      osm[q0*OSM_STRIDE + c + 1] += O[j][1];
      osm[q1*OSM_STRIDE + c    ] += O[j][2];
      osm[q1*OSM_STRIDE + c + 1] += O[j][3];
    }
  }
  if (tid < 128){
    inv[tid] = (*gamma_p) / (l_sm[tid] + l_sm[128 + tid]);
  }
  __syncthreads();

  #pragma unroll
  for (int cc = 0; cc < 8; cc++){
    int c = warp + 16*cc;
    size_t rowbase = ((size_t)b*CCH + c)*NN + n0;
    #pragma unroll
    for (int nn = 0; nn < 4; nn++){
      int n = lane + 32*nn;
      out[rowbase + n] = osm[n*OSM_STRIDE + c]*inv[n] + x[rowbase + n];
    }
  }
}

extern "C" void kernel_launch(void* const* d_in, const int* in_sizes, int n_in,
                              void* d_out, int out_size) {
  const float* x  = (const float*)d_in[0];
  const float* qw = (const float*)d_in[1];
  const float* qb = (const float*)d_in[2];
  const float* kw = (const float*)d_in[3];
  const float* kb = (const float*)d_in[4];
  const float* vw = (const float*)d_in[5];
  const float* vb = (const float*)d_in[6];
  const float* gm = (const float*)d_in[7];
  float* out = (float*)d_out;

  const int proj_smem = 128*XS_STRIDE*2 + NCO*WS_STRIDE*2 + NCO*4;
  cudaFuncSetAttribute(qkv_proj_kernel, cudaFuncAttributeMaxDynamicSharedMemorySize, proj_smem);
  cudaFuncSetAttribute(attn12_kernel,   cudaFuncAttributeMaxDynamicSharedMemorySize, SM_TOTAL);

  qkv_proj_kernel<<<BB*32, 256, proj_smem>>>(x, qw, qb, kw, kb, vw, vb);
  attn12_kernel<<<BB*32, 512, SM_TOTAL>>>(x, gm, out);
}